// round 2
// baseline (speedup 1.0000x reference)
#include <cuda_runtime.h>
#include <cstddef>

#define MAX_N 50000
#define MAX_E 800000
#define D 64

// Scratch (device globals — no allocation allowed)
__device__ __align__(16) float g_aS[MAX_N];
__device__ __align__(16) float g_aD[MAX_N];
__device__ __align__(16) float g_denom[MAX_N];
__device__ __align__(16) float g_zN[(size_t)MAX_N * D];   // sum ex * nfeats[src]
__device__ __align__(16) float g_zE[(size_t)MAX_N * D];   // sum ex * efeats
__device__ __align__(16) float g_Wbig[192 * 64];          // [Wo1; W1@Wo2; W2@Wo2]
__device__ int g_cnt[MAX_N];
__device__ int g_off[MAX_N + 1];
__device__ int g_cur[MAX_N];
__device__ int g_perm[MAX_E];

// ---------------------------------------------------------------------------
// K0: fold weights.  Wbig rows 0-63 = W_out[0:64],
// rows 64-127 = W_ne[0:64]@W_out[64:128], rows 128-191 = W_ne[64:128]@W_out[64:128].
// ---------------------------------------------------------------------------
__global__ void fold_kernel(const float* __restrict__ Wne,
                            const float* __restrict__ Wout) {
    int b = blockIdx.x;          // 0..191
    int j = threadIdx.x;         // 0..63
    if (b < 64) {
        g_Wbig[b * 64 + j] = Wout[b * 64 + j];
    } else {
        int i = b - 64;
        float acc = 0.f;
#pragma unroll 16
        for (int k = 0; k < 64; ++k)
            acc += Wne[i * 64 + k] * Wout[(64 + k) * 64 + j];
        g_Wbig[b * 64 + j] = acc;
    }
}

// ---------------------------------------------------------------------------
// K1: per-node attention scalars a_src, a_dst; zero the dst histogram.
// ---------------------------------------------------------------------------
__global__ void node_pre_kernel(const float* __restrict__ nf,
                                const float* __restrict__ Wattn, int N) {
    int warp = (blockIdx.x * blockDim.x + threadIdx.x) >> 5;
    int lane = threadIdx.x & 31;
    if (warp >= N) return;

    const float4* x4p = (const float4*)(nf + (size_t)warp * D);
    float4 x = __ldg(x4p + (lane & 15));
    float4 w = __ldg(((const float4*)Wattn) + lane);   // lanes 16-31: Wa[64:128]
    float part = x.x * w.x + x.y * w.y + x.z * w.z + x.w * w.w;
    part += __shfl_xor_sync(0xffffffffu, part, 8);
    part += __shfl_xor_sync(0xffffffffu, part, 4);
    part += __shfl_xor_sync(0xffffffffu, part, 2);
    part += __shfl_xor_sync(0xffffffffu, part, 1);
    if (lane == 0)  g_aS[warp] = part;
    if (lane == 16) g_aD[warp] = part;
    if (lane == 1)  g_cnt[warp] = 0;
}

// ---------------------------------------------------------------------------
// K2: histogram of dst
// ---------------------------------------------------------------------------
__global__ void hist_kernel(const int* __restrict__ dst, int E) {
    int e = blockIdx.x * blockDim.x + threadIdx.x;
    if (e < E) atomicAdd(&g_cnt[__ldg(dst + e)], 1);
}

// ---------------------------------------------------------------------------
// K3: exclusive prefix sum over g_cnt -> g_off, g_cur. Single block, 1024 thr.
// ---------------------------------------------------------------------------
__global__ void scan_kernel(int N) {
    __shared__ int sums[1024];
    int t = threadIdx.x;
    int C = (N + 1023) >> 10;
    int lo = t * C;
    int hi = lo + C; if (hi > N) hi = N;
    int s = 0;
    for (int i = lo; i < hi; ++i) s += g_cnt[i];
    sums[t] = s;
    __syncthreads();
    for (int off = 1; off < 1024; off <<= 1) {
        int v = (t >= off) ? sums[t - off] : 0;
        __syncthreads();
        sums[t] += v;
        __syncthreads();
    }
    int pre = (t == 0) ? 0 : sums[t - 1];
    for (int i = lo; i < hi; ++i) {
        g_off[i] = pre;
        g_cur[i] = pre;
        pre += g_cnt[i];
    }
    if (t == 1023) g_off[N] = sums[1023];
}

// ---------------------------------------------------------------------------
// K4: scatter edge ids into dst-sorted order
// ---------------------------------------------------------------------------
__global__ void scatter_kernel(const int* __restrict__ dst, int E) {
    int e = blockIdx.x * blockDim.x + threadIdx.x;
    if (e < E) {
        int d = __ldg(dst + e);
        int pos = atomicAdd(&g_cur[d], 1);
        g_perm[pos] = e;
    }
}

// ---------------------------------------------------------------------------
// K5: gather-aggregate. One warp per dst node, register accumulation, single
// write per node row. No float atomics at all.
// ---------------------------------------------------------------------------
__global__ void gather_kernel(const float* __restrict__ ef,
                              const float* __restrict__ nf,
                              const float* __restrict__ Wattn,
                              const float* __restrict__ b_attn,
                              const int* __restrict__ src, int N) {
    int n = (blockIdx.x * blockDim.x + threadIdx.x) >> 5;
    if (n >= N) return;
    int lane = threadIdx.x & 31;

    float2 wa = __ldg((const float2*)(Wattn + 128) + lane);
    float aDn = g_aD[n];
    float bb = __ldg(b_attn);
    int i0 = g_off[n], i1 = g_off[n + 1];

    float2 aE = make_float2(0.f, 0.f);
    float2 aN = make_float2(0.f, 0.f);
    float den = 0.f;

    for (int i = i0; i < i1; ++i) {
        int e = g_perm[i];
        int s = __ldg(src + e);
        float2 e2 = __ldg((const float2*)ef + (size_t)e * 32 + lane);
        float2 n2 = __ldg((const float2*)nf + (size_t)s * 32 + lane);
        float p = e2.x * wa.x + e2.y * wa.y;
        p += __shfl_xor_sync(0xffffffffu, p, 16);
        p += __shfl_xor_sync(0xffffffffu, p, 8);
        p += __shfl_xor_sync(0xffffffffu, p, 4);
        p += __shfl_xor_sync(0xffffffffu, p, 2);
        p += __shfl_xor_sync(0xffffffffu, p, 1);
        float att = g_aS[s] + aDn + p + bb;
        att = att > 0.f ? att : 0.01f * att;          // leaky_relu
        float ex = __expf(att);                        // max elided (|att|<~10)
        den += ex;
        aE.x += ex * e2.x; aE.y += ex * e2.y;
        aN.x += ex * n2.x; aN.y += ex * n2.y;
    }

    ((float2*)(g_zE + (size_t)n * D))[lane] = aE;
    ((float2*)(g_zN + (size_t)n * D))[lane] = aN;
    if (lane == 0) g_denom[n] = den;
}

// ---------------------------------------------------------------------------
// K6: fused output GEMM.  out = relu(A @ Wbig),
// A[n] = [nfeats[n] | r*zN[n] | r*zE[n]], r = denom>0 ? 1/denom : 0.
// 128 threads, block tile 128x64, BK=32, 8x8 microtile.
// ---------------------------------------------------------------------------
#define BM 128
#define BK 32
#define AS_LD 132
#define BS_LD 68

__global__ __launch_bounds__(128) void out_gemm_kernel(const float* __restrict__ nf,
                                                       float* __restrict__ out, int N) {
    __shared__ float As[BK * AS_LD];
    __shared__ float Bs[BK * BS_LD];
    __shared__ float rr[BM];

    int tid = threadIdx.x;
    int n0 = blockIdx.x * BM;
    int tx = tid & 7;       // col group (8 cols each)
    int ty = tid >> 3;      // row group (8 rows each)

    {
        int n = n0 + tid;
        float dd = (n < N) ? g_denom[n] : 0.f;
        rr[tid] = dd > 0.f ? 1.f / dd : 0.f;
    }

    float acc[8][8];
#pragma unroll
    for (int i = 0; i < 8; ++i)
#pragma unroll
        for (int j = 0; j < 8; ++j) acc[i][j] = 0.f;

    for (int c = 0; c < 6; ++c) {
        const float* Sp = (c < 2) ? nf : (c < 4 ? g_zN : g_zE);
        int colb = (c & 1) * 32;
        bool scale = (c >= 2);
        __syncthreads();
        // A tile: 128 rows x 32 cols, transposed into As[k][row]
#pragma unroll
        for (int l = 0; l < 8; ++l) {
            int idx = l * 128 + tid;
            int row = idx & 127;
            int f4  = idx >> 7;
            int n = n0 + row;
            float4 v = make_float4(0.f, 0.f, 0.f, 0.f);
            if (n < N) v = __ldg((const float4*)(Sp + (size_t)n * 64 + colb) + f4);
            if (scale) { float r = rr[row]; v.x *= r; v.y *= r; v.z *= r; v.w *= r; }
            As[(4 * f4 + 0) * AS_LD + row] = v.x;
            As[(4 * f4 + 1) * AS_LD + row] = v.y;
            As[(4 * f4 + 2) * AS_LD + row] = v.z;
            As[(4 * f4 + 3) * AS_LD + row] = v.w;
        }
        // B tile: 32 x 64
#pragma unroll
        for (int l = 0; l < 4; ++l) {
            int idx = l * 128 + tid;
            int k  = idx >> 4;
            int f4 = idx & 15;
            *(float4*)&Bs[k * BS_LD + 4 * f4] =
                *(const float4*)(g_Wbig + (size_t)(c * 32 + k) * 64 + 4 * f4);
        }
        __syncthreads();
#pragma unroll
        for (int k = 0; k < BK; ++k) {
            float4 a0 = *(const float4*)&As[k * AS_LD + ty * 8];
            float4 a1 = *(const float4*)&As[k * AS_LD + ty * 8 + 4];
            float4 b0 = *(const float4*)&Bs[k * BS_LD + tx * 8];
            float4 b1 = *(const float4*)&Bs[k * BS_LD + tx * 8 + 4];
            float av[8] = {a0.x, a0.y, a0.z, a0.w, a1.x, a1.y, a1.z, a1.w};
            float bv[8] = {b0.x, b0.y, b0.z, b0.w, b1.x, b1.y, b1.z, b1.w};
#pragma unroll
            for (int i = 0; i < 8; ++i)
#pragma unroll
                for (int j = 0; j < 8; ++j)
                    acc[i][j] += av[i] * bv[j];
        }
    }

#pragma unroll
    for (int i = 0; i < 8; ++i) {
        int n = n0 + ty * 8 + i;
        if (n < N) {
            float4 o0, o1;
            o0.x = fmaxf(acc[i][0], 0.f); o0.y = fmaxf(acc[i][1], 0.f);
            o0.z = fmaxf(acc[i][2], 0.f); o0.w = fmaxf(acc[i][3], 0.f);
            o1.x = fmaxf(acc[i][4], 0.f); o1.y = fmaxf(acc[i][5], 0.f);
            o1.z = fmaxf(acc[i][6], 0.f); o1.w = fmaxf(acc[i][7], 0.f);
            *(float4*)(out + (size_t)n * 64 + tx * 8)     = o0;
            *(float4*)(out + (size_t)n * 64 + tx * 8 + 4) = o1;
        }
    }
}

// ---------------------------------------------------------------------------
extern "C" void kernel_launch(void* const* d_in, const int* in_sizes, int n_in,
                              void* d_out, int out_size) {
    const float* nfeats = (const float*)d_in[0];
    const float* efeats = (const float*)d_in[1];
    const float* W_ne   = (const float*)d_in[2];
    const float* W_attn = (const float*)d_in[3];
    const float* b_attn = (const float*)d_in[4];
    const float* W_out  = (const float*)d_in[5];
    const int*   src    = (const int*)d_in[6];
    const int*   dst    = (const int*)d_in[7];
    float* out = (float*)d_out;

    int N = in_sizes[0] / D;
    int E = in_sizes[6];

    fold_kernel<<<192, 64>>>(W_ne, W_out);
    node_pre_kernel<<<(N * 32 + 255) / 256, 256>>>(nfeats, W_attn, N);
    hist_kernel<<<(E + 255) / 256, 256>>>(dst, E);
    scan_kernel<<<1, 1024>>>(N);
    scatter_kernel<<<(E + 255) / 256, 256>>>(dst, E);
    gather_kernel<<<(N * 32 + 255) / 256, 256>>>(efeats, nfeats, W_attn, b_attn, src, N);
    out_gemm_kernel<<<(N + BM - 1) / BM, BM>>>(nfeats, out, N);
}